// round 13
// baseline (speedup 1.0000x reference)
#include <cuda_runtime.h>
#include <cuda_fp16.h>
#include <math.h>
#include <stdint.h>

#define TSEQ   2048
#define BATCH  2
#define CDIM   1024
#define NHEAD  16
#define HD     64
#define WIN    256
#define MROWS  (BATCH*TSEQ)   /* 4096 */

// Scratch (allocation-free rule: __device__ globals; uint16 = half storage)
static __device__ unsigned short g_q[(size_t)MROWS*CDIM];
static __device__ unsigned short g_k[(size_t)MROWS*CDIM];
static __device__ unsigned short g_v[(size_t)MROWS*CDIM];
static __device__ unsigned short g_y[(size_t)MROWS*CDIM];
static __device__ unsigned short g_xh[(size_t)MROWS*CDIM];
static __device__ unsigned short g_wh[4][(size_t)CDIM*CDIM];

// ===========================================================================
// PTX helpers
// ===========================================================================
__device__ __forceinline__ uint32_t smem_u32(const void* p) {
    uint32_t a;
    asm("{ .reg .u64 t; cvta.to.shared.u64 t, %1; cvt.u32.u64 %0, t; }" : "=r"(a) : "l"(p));
    return a;
}
__device__ __forceinline__ void cp_async16(uint32_t s, const void* g) {
    asm volatile("cp.async.cg.shared.global [%0], [%1], 16;" :: "r"(s), "l"(g) : "memory");
}
__device__ __forceinline__ void cp_commit() {
    asm volatile("cp.async.commit_group;" ::: "memory");
}
template <int N_>
__device__ __forceinline__ void cp_wait() {
    asm volatile("cp.async.wait_group %0;" :: "n"(N_) : "memory");
}
__device__ __forceinline__ void mma_f16(float* c, const uint32_t* a, const uint32_t* b) {
    asm volatile(
        "mma.sync.aligned.m16n8k16.row.col.f32.f16.f16.f32 "
        "{%0,%1,%2,%3}, {%4,%5,%6,%7}, {%8,%9}, {%0,%1,%2,%3};"
        : "+f"(c[0]), "+f"(c[1]), "+f"(c[2]), "+f"(c[3])
        : "r"(a[0]), "r"(a[1]), "r"(a[2]), "r"(a[3]), "r"(b[0]), "r"(b[1]));
}
__device__ __forceinline__ void ldmatrix_x4(uint32_t& r0, uint32_t& r1,
                                            uint32_t& r2, uint32_t& r3, uint32_t addr) {
    asm volatile("ldmatrix.sync.aligned.m8n8.x4.shared.b16 {%0,%1,%2,%3}, [%4];"
                 : "=r"(r0), "=r"(r1), "=r"(r2), "=r"(r3) : "r"(addr));
}
__device__ __forceinline__ void ldmatrix_x4t(uint32_t& r0, uint32_t& r1,
                                             uint32_t& r2, uint32_t& r3, uint32_t addr) {
    asm volatile("ldmatrix.sync.aligned.m8n8.x4.trans.shared.b16 {%0,%1,%2,%3}, [%4];"
                 : "=r"(r0), "=r"(r1), "=r"(r2), "=r"(r3) : "r"(addr));
}

// ===========================================================================
// Fused prepass: float -> half for X and all 4 weights, one launch.
// ===========================================================================
#define NX4 (MROWS * CDIM / 4)
#define NW4 (CDIM * CDIM / 4)

__global__ void cvt_all_kernel(const float* __restrict__ x,
                               const float* __restrict__ w0, const float* __restrict__ w1,
                               const float* __restrict__ w2, const float* __restrict__ w3,
                               __half* __restrict__ xh, __half* __restrict__ wh)
{
    int i = blockIdx.x * blockDim.x + threadIdx.x;
    const float* src;
    __half* dst;
    int off;
    if (i < NX4) {
        src = x; dst = xh; off = i;
    } else {
        int j = i - NX4;
        int m = j / NW4;
        off = j - m * NW4;
        src = (m == 0) ? w0 : (m == 1) ? w1 : (m == 2) ? w2 : w3;
        dst = wh + (size_t)m * CDIM * CDIM;
    }
    float4 v = ((const float4*)src)[off];
    ((half2*)dst)[2 * off]     = __floats2half2_rn(v.x, v.y);
    ((half2*)dst)[2 * off + 1] = __floats2half2_rn(v.z, v.w);
}

// ===========================================================================
// fp16 mma GEMM core: Y = Xh @ W + bias (N=K=CDIM fixed).
// CTA 128x128, BK=64, 8 warps (2M x 4N), warp tile 64x32.
// 3-stage cp.async smem pipeline + REGISTER fragment double buffering:
// kk+1 fragments prefetched via ldmatrix while kk's 16 mma issue.
// launch_bounds(256,1) to give ptxas the register headroom (~140 regs).
// ===========================================================================
#define BM 128
#define BN 128
#define BKH 64
#define NSTG 3
#define ASTRH 72    /* halves per A row   (64 + 8 pad)  */
#define BSTRH 136   /* halves per B k-row (128 + 8 pad) */
#define ABYTES (BM * ASTRH * 2)     /* 18432 */
#define BBYTES (BKH * BSTRH * 2)    /* 17408 */
#define STAGEB (ABYTES + BBYTES)    /* 35840 */
#define GEMM_SMEM (NSTG * STAGEB)   /* 107520 */

__device__ __forceinline__ void gemm_core(const __half* __restrict__ X,
                                          const __half* __restrict__ W,
                                          const float* __restrict__ bias,
                                          float* __restrict__ Yf,
                                          __half* __restrict__ Yh,
                                          int m0, int n0, char* dsm)
{
    const int tid  = threadIdx.x;
    const int wid  = tid >> 5;
    const int lane = tid & 31;
    const int wm   = wid & 1;
    const int wn   = wid >> 1;
    const int grp  = lane >> 2;
    const int qid  = lane & 3;

    const uint32_t sbase = smem_u32(dsm);
    uint32_t sAb[NSTG], sBb[NSTG];
#pragma unroll
    for (int s = 0; s < NSTG; s++) {
        sAb[s] = sbase + s * STAGEB;
        sBb[s] = sbase + s * STAGEB + ABYTES;
    }

    float c[4][4][4];
#pragma unroll
    for (int i = 0; i < 4; i++)
#pragma unroll
        for (int j = 0; j < 4; j++)
#pragma unroll
            for (int r = 0; r < 4; r++) c[i][j][r] = 0.f;

    // ldmatrix lane mapping
    const int a_lrow = (lane & 7) + ((lane >> 3) & 1) * 8;
    const int a_lcol = (lane >> 4) * 8;
    const int b_lcol = (lane >> 4) * 8;
    const int b_lrow = lane & 15;
    // per-warp constant smem offsets (element units)
    const uint32_t a_off = (uint32_t)((wm * 64 + a_lrow) * ASTRH + a_lcol);
    const uint32_t b_off0 = (uint32_t)(b_lrow * BSTRH + wn * 32 + b_lcol);
    const uint32_t b_off1 = b_off0 + 16;

    // double-buffered fragments
    uint32_t afb[2][4][4];
    uint32_t bfb[2][2][4];

#define LOAD_STAGE(stg, kk0)                                                       \
    do {                                                                           \
        _Pragma("unroll")                                                          \
        for (int _q = 0; _q < 4; _q++) {                                           \
            int _t = _q * 256 + tid; int _r = _t >> 3, _c = _t & 7;                \
            cp_async16(sAb[(stg)] + (uint32_t)(_r * ASTRH + _c * 8) * 2,           \
                       &X[(size_t)(m0 + _r) * CDIM + (kk0) + _c * 8]);             \
        }                                                                          \
        _Pragma("unroll")                                                          \
        for (int _q = 0; _q < 4; _q++) {                                           \
            int _t = _q * 256 + tid; int _r = _t >> 4, _c = _t & 15;               \
            cp_async16(sBb[(stg)] + (uint32_t)(_r * BSTRH + _c * 8) * 2,           \
                       &W[(size_t)((kk0) + _r) * CDIM + n0 + _c * 8]);             \
        }                                                                          \
    } while (0)

#define LOAD_FRAGS(buf, sAa, sBa, kb)                                              \
    do {                                                                           \
        _Pragma("unroll")                                                          \
        for (int _i = 0; _i < 4; _i++)                                             \
            ldmatrix_x4(afb[buf][_i][0], afb[buf][_i][1],                          \
                        afb[buf][_i][2], afb[buf][_i][3],                          \
                        (sAa) + (a_off + (uint32_t)(_i * 16 * ASTRH + (kb))) * 2); \
        ldmatrix_x4t(bfb[buf][0][0], bfb[buf][0][1], bfb[buf][0][2],               \
                     bfb[buf][0][3], (sBa) + (b_off0 + (uint32_t)((kb) * BSTRH)) * 2); \
        ldmatrix_x4t(bfb[buf][1][0], bfb[buf][1][1], bfb[buf][1][2],               \
                     bfb[buf][1][3], (sBa) + (b_off1 + (uint32_t)((kb) * BSTRH)) * 2); \
    } while (0)

#define DO_MMA(buf)                                                                \
    do {                                                                           \
        _Pragma("unroll")                                                          \
        for (int _jp = 0; _jp < 2; _jp++) {                                        \
            _Pragma("unroll")                                                      \
            for (int _i = 0; _i < 4; _i++) {                                       \
                mma_f16(c[_i][_jp * 2],     afb[buf][_i], &bfb[buf][_jp][0]);      \
                mma_f16(c[_i][_jp * 2 + 1], afb[buf][_i], &bfb[buf][_jp][2]);      \
            }                                                                      \
        }                                                                          \
    } while (0)

    // prologue: smem stages 0..NSTG-2
#pragma unroll
    for (int ps = 0; ps < NSTG - 1; ps++) {
        LOAD_STAGE(ps, ps * BKH);
        cp_commit();
    }

    const int NIT = CDIM / BKH;   // 16
    for (int kt = 0; kt < NIT; kt++) {
        cp_wait<NSTG - 2>();
        __syncthreads();

        if (kt + NSTG - 1 < NIT)
            LOAD_STAGE((kt + NSTG - 1) % NSTG, (kt + NSTG - 1) * BKH);
        cp_commit();

        const int st = kt % NSTG;
        const uint32_t sAa = sAb[st];
        const uint32_t sBa = sBb[st];

        LOAD_FRAGS(0, sAa, sBa, 0);
#pragma unroll
        for (int kk = 0; kk < 4; kk++) {
            const int cur = kk & 1;
            if (kk < 3)
                LOAD_FRAGS(cur ^ 1, sAa, sBa, (kk + 1) * 16);
            DO_MMA(cur);
        }
    }

#pragma unroll
    for (int i = 0; i < 4; i++) {
        const int row = m0 + wm * 64 + i * 16 + grp;
#pragma unroll
        for (int j = 0; j < 4; j++) {
            const int col = n0 + wn * 32 + j * 8 + 2 * qid;
            const float b0 = bias[col], b1 = bias[col + 1];
            const float o0 = c[i][j][0] + b0, o1 = c[i][j][1] + b1;
            const float o2 = c[i][j][2] + b0, o3 = c[i][j][3] + b1;
            if (Yh) {
                *(half2*)&Yh[(size_t)row * CDIM + col]       = __floats2half2_rn(o0, o1);
                *(half2*)&Yh[(size_t)(row + 8) * CDIM + col] = __floats2half2_rn(o2, o3);
            } else {
                float2 v0 = { o0, o1 }, v1 = { o2, o3 };
                *(float2*)&Yf[(size_t)row * CDIM + col]       = v0;
                *(float2*)&Yf[(size_t)(row + 8) * CDIM + col] = v1;
            }
        }
    }
#undef LOAD_STAGE
#undef LOAD_FRAGS
#undef DO_MMA
}

// Fused QKV projection: grid.x = 24 (3 matrices x 8 col-tiles), grid.y = 32.
__global__ __launch_bounds__(256, 1)
void gemm_qkv_kernel(const __half* __restrict__ X, const __half* __restrict__ whBase,
                     const float* __restrict__ bq, const float* __restrict__ bk,
                     const float* __restrict__ bv,
                     __half* __restrict__ qo, __half* __restrict__ ko,
                     __half* __restrict__ vo)
{
    extern __shared__ __align__(16) char dsm_g[];
    const int msel = blockIdx.x >> 3;
    const int n0   = (blockIdx.x & 7) * BN;
    const int m0   = blockIdx.y * BM;
    const __half* W = whBase + (size_t)msel * CDIM * CDIM;
    const float* bias = (msel == 0) ? bq : (msel == 1) ? bk : bv;
    __half* Yh = (msel == 0) ? qo : (msel == 1) ? ko : vo;
    gemm_core(X, W, bias, nullptr, Yh, m0, n0, dsm_g);
}

// Out projection: float output.
__global__ __launch_bounds__(256, 1)
void gemm_out_kernel(const __half* __restrict__ X, const __half* __restrict__ W,
                     const float* __restrict__ bias, float* __restrict__ Yf)
{
    extern __shared__ __align__(16) char dsm_g[];
    gemm_core(X, W, bias, Yf, nullptr, blockIdx.y * BM, blockIdx.x * BN, dsm_g);
}

// ---------------------------------------------------------------------------
// Sliding-window flash attention, Q-tile 128 x K-tile 64, fp16 mma.
// (unchanged from R12)
// ---------------------------------------------------------------------------
#define QR    128
#define QSTRH 72
#define KSTRH 72
#define VSTRH 72
#define PSTRH 72
#define SSTR  68
#define ATT_SMEM_B ((QR*QSTRH + 64*KSTRH + 64*VSTRH + QR*PSTRH) * 2 + QR*SSTR*4)

__global__ __launch_bounds__(256)
void attn_kernel(const __half* __restrict__ qg, const __half* __restrict__ kg,
                 const __half* __restrict__ vg, __half* __restrict__ yg)
{
    extern __shared__ __align__(16) char dsm[];
    __half* qs = (__half*)dsm;
    __half* ks = qs + QR * QSTRH;
    __half* vs = ks + 64 * KSTRH;
    __half* ps = vs + 64 * VSTRH;
    float*  ss = (float*)(ps + QR * PSTRH);
    __shared__ float mrow[QR], lrow[QR], arow[QR];

    const int tid  = threadIdx.x;
    const int wid  = tid >> 5;
    const int lane = tid & 31;
    const int grp  = lane >> 2;
    const int qid  = lane & 3;
    const int rw0  = wid * 16;
    const uint32_t vs_u32 = smem_u32(vs);

    const int qt = blockIdx.x;
    const int h  = blockIdx.y;
    const int b  = blockIdx.z;
    const int q0 = qt * QR;
    const size_t base = ((size_t)b * TSEQ) * CDIM + (size_t)h * HD;

    for (int e = tid; e < QR * 32; e += 256) {
        int r = e >> 5, c2 = e & 31;
        *(half2*)&qs[r * QSTRH + 2 * c2] =
            *(const half2*)&qg[base + (size_t)(q0 + r) * CDIM + 2 * c2];
    }
    if (tid < QR) { mrow[tid] = -INFINITY; lrow[tid] = 0.f; }

    float oacc[8][4];
#pragma unroll
    for (int j = 0; j < 8; j++)
#pragma unroll
        for (int r = 0; r < 4; r++) oacc[j][r] = 0.f;
    __syncthreads();

    const int kt_lo = (q0 >= WIN) ? ((q0 - WIN) >> 6) : 0;
    const int kt_hi = (q0 >> 6) + 1;
    for (int kt = kt_lo; kt <= kt_hi; kt++) {
        const int k0 = kt * 64;
        for (int e = tid; e < 64 * 32; e += 256) {
            int r = e >> 5, c2 = e & 31;
            *(half2*)&ks[r * KSTRH + 2 * c2] =
                *(const half2*)&kg[base + (size_t)(k0 + r) * CDIM + 2 * c2];
            *(half2*)&vs[r * VSTRH + 2 * c2] =
                *(const half2*)&vg[base + (size_t)(k0 + r) * CDIM + 2 * c2];
        }
        __syncthreads();

        const int i_lo = q0 + rw0;
        const int i_hi = i_lo + 15;
        const bool full_invalid = (k0 > i_hi) || (i_lo - (k0 + 63) > WIN);
        const bool full_valid   = (k0 + 63 <= i_lo) && (i_hi - k0 <= WIN);

        const int r0 = rw0 + grp;
        if (full_invalid) {
#pragma unroll
            for (int j = 0; j < 8; j++) {
                const int col = j * 8 + 2 * qid;
                ss[r0 * SSTR + col]           = -INFINITY;
                ss[r0 * SSTR + col + 1]       = -INFINITY;
                ss[(r0 + 8) * SSTR + col]     = -INFINITY;
                ss[(r0 + 8) * SSTR + col + 1] = -INFINITY;
            }
        } else {
            float sacc[8][4];
#pragma unroll
            for (int j = 0; j < 8; j++)
#pragma unroll
                for (int r = 0; r < 4; r++) sacc[j][r] = 0.f;
#pragma unroll
            for (int ks16 = 0; ks16 < 4; ks16++) {
                const int kb = ks16 * 16;
                uint32_t af[4];
                af[0] = *(const uint32_t*)&qs[r0 * QSTRH + kb + 2 * qid];
                af[1] = *(const uint32_t*)&qs[(r0 + 8) * QSTRH + kb + 2 * qid];
                af[2] = *(const uint32_t*)&qs[r0 * QSTRH + kb + 2 * qid + 8];
                af[3] = *(const uint32_t*)&qs[(r0 + 8) * QSTRH + kb + 2 * qid + 8];
#pragma unroll
                for (int j = 0; j < 8; j++) {
                    const int cn = j * 8 + grp;
                    uint32_t bf[2];
                    bf[0] = *(const uint32_t*)&ks[cn * KSTRH + kb + 2 * qid];
                    bf[1] = *(const uint32_t*)&ks[cn * KSTRH + kb + 2 * qid + 8];
                    mma_f16(sacc[j], af, bf);
                }
            }
            if (full_valid) {
#pragma unroll
                for (int j = 0; j < 8; j++) {
                    const int col = j * 8 + 2 * qid;
                    ss[r0 * SSTR + col]           = sacc[j][0] * 0.125f;
                    ss[r0 * SSTR + col + 1]       = sacc[j][1] * 0.125f;
                    ss[(r0 + 8) * SSTR + col]     = sacc[j][2] * 0.125f;
                    ss[(r0 + 8) * SSTR + col + 1] = sacc[j][3] * 0.125f;
                }
            } else {
#pragma unroll
                for (int j = 0; j < 8; j++) {
                    const int col = j * 8 + 2 * qid;
                    const int gi0 = q0 + r0, gi1 = gi0 + 8;
                    const int gj0 = k0 + col, gj1 = gj0 + 1;
                    const int d00 = gi0 - gj0, d01 = gi0 - gj1;
                    const int d10 = gi1 - gj0, d11 = gi1 - gj1;
                    ss[r0 * SSTR + col] =
                        (d00 >= 0 && d00 <= WIN) ? sacc[j][0] * 0.125f : -INFINITY;
                    ss[r0 * SSTR + col + 1] =
                        (d01 >= 0 && d01 <= WIN) ? sacc[j][1] * 0.125f : -INFINITY;
                    ss[(r0 + 8) * SSTR + col] =
                        (d10 >= 0 && d10 <= WIN) ? sacc[j][2] * 0.125f : -INFINITY;
                    ss[(r0 + 8) * SSTR + col + 1] =
                        (d11 >= 0 && d11 <= WIN) ? sacc[j][3] * 0.125f : -INFINITY;
                }
            }
        }
        __syncthreads();

        {
            const int row = tid >> 1, seg = tid & 1;
            float* srow = ss + row * SSTR + seg * 32;
            __half* prow = ps + row * PSTRH + seg * 32;
            float mloc = -INFINITY;
#pragma unroll
            for (int c2 = 0; c2 < 32; c2++) mloc = fmaxf(mloc, srow[c2]);
            mloc = fmaxf(mloc, __shfl_xor_sync(0xffffffffu, mloc, 1));
            const float mold = mrow[row];
            const float mnew = fmaxf(mold, mloc);
            const float msub = fmaxf(mnew, -1e30f);
            const float al   = __expf(mold - msub);
            float suml = 0.f;
#pragma unroll
            for (int c2 = 0; c2 < 32; c2 += 2) {
                float p0 = __expf(srow[c2] - msub);
                float p1 = __expf(srow[c2 + 1] - msub);
                suml += p0 + p1;
                *(half2*)&prow[c2] = __floats2half2_rn(p0, p1);
            }
            suml += __shfl_xor_sync(0xffffffffu, suml, 1);
            if (seg == 0) {
                mrow[row] = mnew;
                lrow[row] = lrow[row] * al + suml;
                arow[row] = al;
            }
        }
        __syncthreads();

        {
            const float a_lo = arow[rw0 + grp];
            const float a_hi = arow[rw0 + grp + 8];
#pragma unroll
            for (int j = 0; j < 8; j++) {
                oacc[j][0] *= a_lo; oacc[j][1] *= a_lo;
                oacc[j][2] *= a_hi; oacc[j][3] *= a_hi;
            }
        }
        const int r0b = rw0 + grp;
#pragma unroll
        for (int ks16 = 0; ks16 < 4; ks16++) {
            const int kb = ks16 * 16;
            uint32_t af[4];
            af[0] = *(const uint32_t*)&ps[r0b * PSTRH + kb + 2 * qid];
            af[1] = *(const uint32_t*)&ps[(r0b + 8) * PSTRH + kb + 2 * qid];
            af[2] = *(const uint32_t*)&ps[r0b * PSTRH + kb + 2 * qid + 8];
            af[3] = *(const uint32_t*)&ps[(r0b + 8) * PSTRH + kb + 2 * qid + 8];
#pragma unroll
            for (int jp = 0; jp < 4; jp++) {
                const int col  = jp * 16 + ((lane >> 4) << 3);
                const int krow = kb + (lane & 15);
                uint32_t b0, b1, b2, b3;
                ldmatrix_x4t(b0, b1, b2, b3,
                             vs_u32 + (uint32_t)(krow * VSTRH + col) * 2);
                uint32_t bj0[2] = { b0, b1 };
                uint32_t bj1[2] = { b2, b3 };
                mma_f16(oacc[jp * 2],     af, bj0);
                mma_f16(oacc[jp * 2 + 1], af, bj1);
            }
        }
        __syncthreads();
    }

    {
        const int r0 = rw0 + grp;
        const float inv_lo = 1.0f / lrow[r0];
        const float inv_hi = 1.0f / lrow[r0 + 8];
#pragma unroll
        for (int j = 0; j < 8; j++) {
            const int col = j * 8 + 2 * qid;
            *(half2*)&yg[base + (size_t)(q0 + r0) * CDIM + col] =
                __floats2half2_rn(oacc[j][0] * inv_lo, oacc[j][1] * inv_lo);
            *(half2*)&yg[base + (size_t)(q0 + r0 + 8) * CDIM + col] =
                __floats2half2_rn(oacc[j][2] * inv_hi, oacc[j][3] * inv_hi);
        }
    }
}

// ---------------------------------------------------------------------------
extern "C" void kernel_launch(void* const* d_in, const int* in_sizes, int n_in,
                              void* d_out, int out_size)
{
    const float* x  = (const float*)d_in[0];
    const float* Wq = (const float*)d_in[1];
    const float* bq = (const float*)d_in[2];
    const float* Wk = (const float*)d_in[3];
    const float* bk = (const float*)d_in[4];
    const float* Wv = (const float*)d_in[5];
    const float* bv = (const float*)d_in[6];
    const float* Wo = (const float*)d_in[7];
    const float* bo = (const float*)d_in[8];
    float* out = (float*)d_out;
    (void)in_sizes; (void)n_in; (void)out_size;

    __half *qp, *kp, *vp, *yp, *xhp, *whp;
    cudaGetSymbolAddress((void**)&qp,  g_q);
    cudaGetSymbolAddress((void**)&kp,  g_k);
    cudaGetSymbolAddress((void**)&vp,  g_v);
    cudaGetSymbolAddress((void**)&yp,  g_y);
    cudaGetSymbolAddress((void**)&xhp, g_xh);
    cudaGetSymbolAddress((void**)&whp, g_wh);
    __half* who = whp + 3 * (size_t)CDIM * CDIM;

    cudaFuncSetAttribute(attn_kernel,
                         cudaFuncAttributeMaxDynamicSharedMemorySize, ATT_SMEM_B);
    cudaFuncSetAttribute(gemm_qkv_kernel,
                         cudaFuncAttributeMaxDynamicSharedMemorySize, GEMM_SMEM);
    cudaFuncSetAttribute(gemm_out_kernel,
                         cudaFuncAttributeMaxDynamicSharedMemorySize, GEMM_SMEM);

    const int TOT4 = NX4 + 4 * NW4;
    cvt_all_kernel<<<(TOT4 + 255) / 256, 256>>>(x, Wq, Wk, Wv, Wo, xhp, whp);

    gemm_qkv_kernel<<<dim3(24, MROWS / BM), 256, GEMM_SMEM>>>(xhp, whp, bq, bk, bv,
                                                              qp, kp, vp);

    attn_kernel<<<dim3(TSEQ / QR, NHEAD, BATCH), 256, ATT_SMEM_B>>>(qp, kp, vp, yp);

    gemm_out_kernel<<<dim3(CDIM / BN, MROWS / BM), 256, GEMM_SMEM>>>(yp, who, bo, out);
}

// round 14
// speedup vs baseline: 1.3527x; 1.3527x over previous
#include <cuda_runtime.h>
#include <cuda_fp16.h>
#include <math.h>
#include <stdint.h>

#define TSEQ   2048
#define BATCH  2
#define CDIM   1024
#define NHEAD  16
#define HD     64
#define WIN    256
#define MROWS  (BATCH*TSEQ)   /* 4096 */

// Scratch (allocation-free rule: __device__ globals; uint16 = half storage)
static __device__ unsigned short g_q[(size_t)MROWS*CDIM];
static __device__ unsigned short g_k[(size_t)MROWS*CDIM];
static __device__ unsigned short g_v[(size_t)MROWS*CDIM];
static __device__ unsigned short g_y[(size_t)MROWS*CDIM];
static __device__ unsigned short g_xh[(size_t)MROWS*CDIM];
static __device__ unsigned short g_wh[4][(size_t)CDIM*CDIM];

// ===========================================================================
// PTX helpers
// ===========================================================================
__device__ __forceinline__ uint32_t smem_u32(const void* p) {
    uint32_t a;
    asm("{ .reg .u64 t; cvta.to.shared.u64 t, %1; cvt.u32.u64 %0, t; }" : "=r"(a) : "l"(p));
    return a;
}
__device__ __forceinline__ void cp_async16(uint32_t s, const void* g) {
    asm volatile("cp.async.cg.shared.global [%0], [%1], 16;" :: "r"(s), "l"(g) : "memory");
}
__device__ __forceinline__ void cp_commit() {
    asm volatile("cp.async.commit_group;" ::: "memory");
}
template <int N_>
__device__ __forceinline__ void cp_wait() {
    asm volatile("cp.async.wait_group %0;" :: "n"(N_) : "memory");
}
__device__ __forceinline__ void mma_f16(float* c, const uint32_t* a, const uint32_t* b) {
    asm volatile(
        "mma.sync.aligned.m16n8k16.row.col.f32.f16.f16.f32 "
        "{%0,%1,%2,%3}, {%4,%5,%6,%7}, {%8,%9}, {%0,%1,%2,%3};"
        : "+f"(c[0]), "+f"(c[1]), "+f"(c[2]), "+f"(c[3])
        : "r"(a[0]), "r"(a[1]), "r"(a[2]), "r"(a[3]), "r"(b[0]), "r"(b[1]));
}
__device__ __forceinline__ void ldmatrix_x4(uint32_t& r0, uint32_t& r1,
                                            uint32_t& r2, uint32_t& r3, uint32_t addr) {
    asm volatile("ldmatrix.sync.aligned.m8n8.x4.shared.b16 {%0,%1,%2,%3}, [%4];"
                 : "=r"(r0), "=r"(r1), "=r"(r2), "=r"(r3) : "r"(addr));
}
__device__ __forceinline__ void ldmatrix_x4t(uint32_t& r0, uint32_t& r1,
                                             uint32_t& r2, uint32_t& r3, uint32_t addr) {
    asm volatile("ldmatrix.sync.aligned.m8n8.x4.trans.shared.b16 {%0,%1,%2,%3}, [%4];"
                 : "=r"(r0), "=r"(r1), "=r"(r2), "=r"(r3) : "r"(addr));
}
__device__ __forceinline__ uint32_t packh2(float a, float b) {
    half2 h = __floats2half2_rn(a, b);
    return *(uint32_t*)&h;
}

// ===========================================================================
// Fused prepass: float -> half for X and all 4 weights, one launch.
// ===========================================================================
#define NX4 (MROWS * CDIM / 4)
#define NW4 (CDIM * CDIM / 4)

__global__ void cvt_all_kernel(const float* __restrict__ x,
                               const float* __restrict__ w0, const float* __restrict__ w1,
                               const float* __restrict__ w2, const float* __restrict__ w3,
                               __half* __restrict__ xh, __half* __restrict__ wh)
{
    int i = blockIdx.x * blockDim.x + threadIdx.x;
    const float* src;
    __half* dst;
    int off;
    if (i < NX4) {
        src = x; dst = xh; off = i;
    } else {
        int j = i - NX4;
        int m = j / NW4;
        off = j - m * NW4;
        src = (m == 0) ? w0 : (m == 1) ? w1 : (m == 2) ? w2 : w3;
        dst = wh + (size_t)m * CDIM * CDIM;
    }
    float4 v = ((const float4*)src)[off];
    ((half2*)dst)[2 * off]     = __floats2half2_rn(v.x, v.y);
    ((half2*)dst)[2 * off + 1] = __floats2half2_rn(v.z, v.w);
}

// ===========================================================================
// fp16 mma GEMM core (R12 config — best measured: occ 2, 3-stage, 1 sync/iter)
// ===========================================================================
#define BM 128
#define BN 128
#define BKH 64
#define NSTG 3
#define ASTRH 72
#define BSTRH 136
#define ABYTES (BM * ASTRH * 2)
#define BBYTES (BKH * BSTRH * 2)
#define STAGEB (ABYTES + BBYTES)
#define GEMM_SMEM (NSTG * STAGEB)

__device__ __forceinline__ void gemm_core(const __half* __restrict__ X,
                                          const __half* __restrict__ W,
                                          const float* __restrict__ bias,
                                          float* __restrict__ Yf,
                                          __half* __restrict__ Yh,
                                          int m0, int n0, char* dsm)
{
    const int tid  = threadIdx.x;
    const int wid  = tid >> 5;
    const int lane = tid & 31;
    const int wm   = wid & 1;
    const int wn   = wid >> 1;
    const int grp  = lane >> 2;
    const int qid  = lane & 3;

    const uint32_t sbase = smem_u32(dsm);
    uint32_t sAb[NSTG], sBb[NSTG];
#pragma unroll
    for (int s = 0; s < NSTG; s++) {
        sAb[s] = sbase + s * STAGEB;
        sBb[s] = sbase + s * STAGEB + ABYTES;
    }

    float c[4][4][4];
#pragma unroll
    for (int i = 0; i < 4; i++)
#pragma unroll
        for (int j = 0; j < 4; j++)
#pragma unroll
            for (int r = 0; r < 4; r++) c[i][j][r] = 0.f;

    const int a_lrow = (lane & 7) + ((lane >> 3) & 1) * 8;
    const int a_lcol = (lane >> 4) * 8;
    const int b_lcol = (lane >> 4) * 8;
    const int b_lrow = lane & 15;

#define LOAD_STAGE(stg, kk0)                                                       \
    do {                                                                           \
        _Pragma("unroll")                                                          \
        for (int _q = 0; _q < 4; _q++) {                                           \
            int _t = _q * 256 + tid; int _r = _t >> 3, _c = _t & 7;                \
            cp_async16(sAb[(stg)] + (uint32_t)(_r * ASTRH + _c * 8) * 2,           \
                       &X[(size_t)(m0 + _r) * CDIM + (kk0) + _c * 8]);             \
        }                                                                          \
        _Pragma("unroll")                                                          \
        for (int _q = 0; _q < 4; _q++) {                                           \
            int _t = _q * 256 + tid; int _r = _t >> 4, _c = _t & 15;               \
            cp_async16(sBb[(stg)] + (uint32_t)(_r * BSTRH + _c * 8) * 2,           \
                       &W[(size_t)((kk0) + _r) * CDIM + n0 + _c * 8]);             \
        }                                                                          \
    } while (0)

#pragma unroll
    for (int ps = 0; ps < NSTG - 1; ps++) {
        LOAD_STAGE(ps, ps * BKH);
        cp_commit();
    }

    const int NIT = CDIM / BKH;
    for (int kt = 0; kt < NIT; kt++) {
        cp_wait<NSTG - 2>();
        __syncthreads();

        if (kt + NSTG - 1 < NIT)
            LOAD_STAGE((kt + NSTG - 1) % NSTG, (kt + NSTG - 1) * BKH);
        cp_commit();

        const int st = kt % NSTG;
        const uint32_t sAa = sAb[st];
        const uint32_t sBa = sBb[st];
#pragma unroll
        for (int kk = 0; kk < 4; kk++) {
            const int kb = kk * 16;
            uint32_t af[4][4];
#pragma unroll
            for (int i = 0; i < 4; i++) {
                const int row = wm * 64 + i * 16 + a_lrow;
                ldmatrix_x4(af[i][0], af[i][1], af[i][2], af[i][3],
                            sAa + (uint32_t)(row * ASTRH + kb + a_lcol) * 2);
            }
#pragma unroll
            for (int jp = 0; jp < 2; jp++) {
                const int col  = wn * 32 + jp * 16 + b_lcol;
                const int krow = kb + b_lrow;
                uint32_t b0, b1, b2, b3;
                ldmatrix_x4t(b0, b1, b2, b3, sBa + (uint32_t)(krow * BSTRH + col) * 2);
                uint32_t bj0[2] = { b0, b1 };
                uint32_t bj1[2] = { b2, b3 };
#pragma unroll
                for (int i = 0; i < 4; i++) {
                    mma_f16(c[i][jp * 2],     af[i], bj0);
                    mma_f16(c[i][jp * 2 + 1], af[i], bj1);
                }
            }
        }
    }

#pragma unroll
    for (int i = 0; i < 4; i++) {
        const int row = m0 + wm * 64 + i * 16 + grp;
#pragma unroll
        for (int j = 0; j < 4; j++) {
            const int col = n0 + wn * 32 + j * 8 + 2 * qid;
            const float b0 = bias[col], b1 = bias[col + 1];
            const float o0 = c[i][j][0] + b0, o1 = c[i][j][1] + b1;
            const float o2 = c[i][j][2] + b0, o3 = c[i][j][3] + b1;
            if (Yh) {
                *(half2*)&Yh[(size_t)row * CDIM + col]       = __floats2half2_rn(o0, o1);
                *(half2*)&Yh[(size_t)(row + 8) * CDIM + col] = __floats2half2_rn(o2, o3);
            } else {
                float2 v0 = { o0, o1 }, v1 = { o2, o3 };
                *(float2*)&Yf[(size_t)row * CDIM + col]       = v0;
                *(float2*)&Yf[(size_t)(row + 8) * CDIM + col] = v1;
            }
        }
    }
#undef LOAD_STAGE
}

__global__ __launch_bounds__(256, 2)
void gemm_qkv_kernel(const __half* __restrict__ X, const __half* __restrict__ whBase,
                     const float* __restrict__ bq, const float* __restrict__ bk,
                     const float* __restrict__ bv,
                     __half* __restrict__ qo, __half* __restrict__ ko,
                     __half* __restrict__ vo)
{
    extern __shared__ __align__(16) char dsm_g[];
    const int msel = blockIdx.x >> 3;
    const int n0   = (blockIdx.x & 7) * BN;
    const int m0   = blockIdx.y * BM;
    const __half* W = whBase + (size_t)msel * CDIM * CDIM;
    const float* bias = (msel == 0) ? bq : (msel == 1) ? bk : bv;
    __half* Yh = (msel == 0) ? qo : (msel == 1) ? ko : vo;
    gemm_core(X, W, bias, nullptr, Yh, m0, n0, dsm_g);
}

__global__ __launch_bounds__(256, 2)
void gemm_out_kernel(const __half* __restrict__ X, const __half* __restrict__ W,
                     const float* __restrict__ bias, float* __restrict__ Yf)
{
    extern __shared__ __align__(16) char dsm_g[];
    gemm_core(X, W, bias, Yf, nullptr, blockIdx.y * BM, blockIdx.x * BN, dsm_g);
}

// ---------------------------------------------------------------------------
// FA2-style sliding-window attention: Q-tile 128 x K-tile 64, fp16 mma.
// Register-resident softmax (m/l per thread, quad shfl reductions),
// P reused from S accumulator layout (no smem roundtrip),
// 3-stage cp.async K/V pipeline, 1 barrier per k-tile.
// ---------------------------------------------------------------------------
#define QR     128
#define QSTRH  72
#define KVSTR  72
#define QBYTES (QR * QSTRH * 2)            /* 18432 */
#define KVTILE (64 * KVSTR * 2)            /* 9216 per tensor */
#define KVSTG  (2 * KVTILE)                /* K+V per stage = 18432 */
#define ANSTG  3
#define ATT_SMEM_B (QBYTES + ANSTG * KVSTG) /* 73728 */

__global__ __launch_bounds__(256)
void attn_kernel(const __half* __restrict__ qg, const __half* __restrict__ kg,
                 const __half* __restrict__ vg, __half* __restrict__ yg)
{
    extern __shared__ __align__(16) char dsm[];
    const uint32_t qbase = smem_u32(dsm);
    uint32_t kbase[ANSTG], vbase[ANSTG];
#pragma unroll
    for (int s = 0; s < ANSTG; s++) {
        kbase[s] = qbase + QBYTES + s * KVSTG;
        vbase[s] = kbase[s] + KVTILE;
    }

    const int tid  = threadIdx.x;
    const int wid  = tid >> 5;
    const int lane = tid & 31;
    const int grp  = lane >> 2;
    const int qid  = lane & 3;
    const int rw0  = wid * 16;

    const int qt = blockIdx.x;
    const int h  = blockIdx.y;
    const int b  = blockIdx.z;
    const int q0 = qt * QR;
    const size_t base = ((size_t)b * TSEQ) * CDIM + (size_t)h * HD;

    // ldmatrix lane mappings
    const int a_lrow = (lane & 7) + ((lane >> 3) & 1) * 8;
    const int a_lcol = (lane >> 4) * 8;
    const uint32_t q_off = (uint32_t)((rw0 + a_lrow) * QSTRH + a_lcol);
    // K (B-frag, non-trans): row = (lane&7) + (lane>>4)*8, col += ((lane>>3)&1)*8
    const uint32_t k_off = (uint32_t)(((lane & 7) + (lane >> 4) * 8) * KVSTR +
                                      ((lane >> 3) & 1) * 8);
    // V (B-frag, trans): krow = lane&15, col = (lane>>4)*8
    const uint32_t v_off = (uint32_t)((lane & 15) * KVSTR + (lane >> 4) * 8);

    // Q -> smem
    __half* qsm = (__half*)dsm;
    for (int e = tid; e < QR * 32; e += 256) {
        int r = e >> 5, c2 = e & 31;
        *(half2*)&qsm[r * QSTRH + 2 * c2] =
            *(const half2*)&qg[base + (size_t)(q0 + r) * CDIM + 2 * c2];
    }

#define LOAD_KV(stg, kt_)                                                          \
    do {                                                                           \
        const int _k0 = (kt_) * 64;                                                \
        _Pragma("unroll")                                                          \
        for (int _q = 0; _q < 2; _q++) {                                           \
            int _e = _q * 256 + tid; int _r = _e >> 3, _c = _e & 7;                \
            cp_async16(kbase[(stg)] + (uint32_t)(_r * KVSTR + _c * 8) * 2,         \
                       &kg[base + (size_t)(_k0 + _r) * CDIM + _c * 8]);            \
        }                                                                          \
        _Pragma("unroll")                                                          \
        for (int _q = 0; _q < 2; _q++) {                                           \
            int _e = _q * 256 + tid; int _r = _e >> 3, _c = _e & 7;                \
            cp_async16(vbase[(stg)] + (uint32_t)(_r * KVSTR + _c * 8) * 2,         \
                       &vg[base + (size_t)(_k0 + _r) * CDIM + _c * 8]);            \
        }                                                                          \
    } while (0)

    const int kt_lo = (q0 >= WIN) ? ((q0 - WIN) >> 6) : 0;
    const int kt_hi = (q0 >> 6) + 1;
    const int nkt   = kt_hi - kt_lo + 1;

    // pipeline prologue
    LOAD_KV(0, kt_lo);
    cp_commit();
    if (nkt > 1) LOAD_KV(1, kt_lo + 1);
    cp_commit();

    // per-thread online-softmax state
    float m_lo = -INFINITY, m_hi = -INFINITY;
    float l_lo = 0.f, l_hi = 0.f;
    float oacc[8][4];
#pragma unroll
    for (int j = 0; j < 8; j++)
#pragma unroll
        for (int r = 0; r < 4; r++) oacc[j][r] = 0.f;

    const int r0  = rw0 + grp;
    const int gi0 = q0 + r0, gi1 = gi0 + 8;

    for (int idx = 0; idx < nkt; idx++) {
        cp_wait<1>();
        __syncthreads();
        if (idx + 2 < nkt) LOAD_KV((idx + 2) % ANSTG, kt_lo + idx + 2);
        cp_commit();

        const int kt = kt_lo + idx;
        const int k0 = kt * 64;
        const int st = idx % ANSTG;

        // warp-level tile classification
        const int i_lo = q0 + rw0, i_hi = i_lo + 15;
        if ((k0 > i_hi) || (i_lo - (k0 + 63) > WIN)) continue;   // fully masked
        const bool full_valid = (k0 + 63 <= i_lo) && (i_hi - k0 <= WIN);

        // ---- S = Q K^T (registers) ----
        float sacc[8][4];
#pragma unroll
        for (int j = 0; j < 8; j++)
#pragma unroll
            for (int r = 0; r < 4; r++) sacc[j][r] = 0.f;
#pragma unroll
        for (int ks16 = 0; ks16 < 4; ks16++) {
            const int kb = ks16 * 16;
            uint32_t af[4];
            ldmatrix_x4(af[0], af[1], af[2], af[3], qbase + (q_off + kb) * 2);
#pragma unroll
            for (int jp = 0; jp < 4; jp++) {
                uint32_t b0, b1, b2, b3;
                ldmatrix_x4(b0, b1, b2, b3,
                            kbase[st] + (k_off + (uint32_t)(jp * 16 * KVSTR + kb)) * 2);
                uint32_t bj0[2] = { b0, b1 };
                uint32_t bj1[2] = { b2, b3 };
                mma_f16(sacc[jp * 2],     af, bj0);
                mma_f16(sacc[jp * 2 + 1], af, bj1);
            }
        }

        // ---- scale + mask in registers ----
        if (full_valid) {
#pragma unroll
            for (int j = 0; j < 8; j++)
#pragma unroll
                for (int r = 0; r < 4; r++) sacc[j][r] *= 0.125f;
        } else {
#pragma unroll
            for (int j = 0; j < 8; j++) {
                const int gj0 = k0 + j * 8 + 2 * qid, gj1 = gj0 + 1;
                const int d00 = gi0 - gj0, d01 = gi0 - gj1;
                const int d10 = gi1 - gj0, d11 = gi1 - gj1;
                sacc[j][0] = (d00 >= 0 && d00 <= WIN) ? sacc[j][0] * 0.125f : -INFINITY;
                sacc[j][1] = (d01 >= 0 && d01 <= WIN) ? sacc[j][1] * 0.125f : -INFINITY;
                sacc[j][2] = (d10 >= 0 && d10 <= WIN) ? sacc[j][2] * 0.125f : -INFINITY;
                sacc[j][3] = (d11 >= 0 && d11 <= WIN) ? sacc[j][3] * 0.125f : -INFINITY;
            }
        }

        // ---- online softmax (registers; quad shfl over lanes 4g..4g+3) ----
        float ml = -INFINITY, mh = -INFINITY;
#pragma unroll
        for (int j = 0; j < 8; j++) {
            ml = fmaxf(ml, fmaxf(sacc[j][0], sacc[j][1]));
            mh = fmaxf(mh, fmaxf(sacc[j][2], sacc[j][3]));
        }
        ml = fmaxf(ml, __shfl_xor_sync(0xffffffffu, ml, 1));
        ml = fmaxf(ml, __shfl_xor_sync(0xffffffffu, ml, 2));
        mh = fmaxf(mh, __shfl_xor_sync(0xffffffffu, mh, 1));
        mh = fmaxf(mh, __shfl_xor_sync(0xffffffffu, mh, 2));

        const float mnl = fmaxf(m_lo, ml), mnh = fmaxf(m_hi, mh);
        const float msl = fmaxf(mnl, -1e30f), msh = fmaxf(mnh, -1e30f);
        const float al_lo = __expf(m_lo - msl), al_hi = __expf(m_hi - msh);

        uint32_t ph[8][2];
        float sl = 0.f, sh = 0.f;
#pragma unroll
        for (int j = 0; j < 8; j++) {
            float p0 = __expf(sacc[j][0] - msl);
            float p1 = __expf(sacc[j][1] - msl);
            float p2 = __expf(sacc[j][2] - msh);
            float p3 = __expf(sacc[j][3] - msh);
            sl += p0 + p1;
            sh += p2 + p3;
            ph[j][0] = packh2(p0, p1);
            ph[j][1] = packh2(p2, p3);
        }
        sl += __shfl_xor_sync(0xffffffffu, sl, 1);
        sl += __shfl_xor_sync(0xffffffffu, sl, 2);
        sh += __shfl_xor_sync(0xffffffffu, sh, 1);
        sh += __shfl_xor_sync(0xffffffffu, sh, 2);

        l_lo = l_lo * al_lo + sl;
        l_hi = l_hi * al_hi + sh;
        m_lo = mnl;
        m_hi = mnh;
#pragma unroll
        for (int j = 0; j < 8; j++) {
            oacc[j][0] *= al_lo; oacc[j][1] *= al_lo;
            oacc[j][2] *= al_hi; oacc[j][3] *= al_hi;
        }

        // ---- O += P @ V (P fragments straight from registers) ----
#pragma unroll
        for (int ks16 = 0; ks16 < 4; ks16++) {
            const int kb = ks16 * 16;
            uint32_t af[4];
            af[0] = ph[2 * ks16][0];
            af[1] = ph[2 * ks16][1];
            af[2] = ph[2 * ks16 + 1][0];
            af[3] = ph[2 * ks16 + 1][1];
#pragma unroll
            for (int jp = 0; jp < 4; jp++) {
                uint32_t b0, b1, b2, b3;
                ldmatrix_x4t(b0, b1, b2, b3,
                             vbase[st] + (v_off + (uint32_t)(kb * KVSTR + jp * 16)) * 2);
                uint32_t bj0[2] = { b0, b1 };
                uint32_t bj1[2] = { b2, b3 };
                mma_f16(oacc[jp * 2],     af, bj0);
                mma_f16(oacc[jp * 2 + 1], af, bj1);
            }
        }
    }

    // epilogue: normalize, write y (half)
    {
        const float inv_lo = 1.0f / l_lo;
        const float inv_hi = 1.0f / l_hi;
#pragma unroll
        for (int j = 0; j < 8; j++) {
            const int col = j * 8 + 2 * qid;
            *(half2*)&yg[base + (size_t)(q0 + r0) * CDIM + col] =
                __floats2half2_rn(oacc[j][0] * inv_lo, oacc[j][1] * inv_lo);
            *(half2*)&yg[base + (size_t)(q0 + r0 + 8) * CDIM + col] =
                __floats2half2_rn(oacc[j][2] * inv_hi, oacc[j][3] * inv_hi);
        }
    }
#undef LOAD_KV
}

// ---------------------------------------------------------------------------
extern "C" void kernel_launch(void* const* d_in, const int* in_sizes, int n_in,
                              void* d_out, int out_size)
{
    const float* x  = (const float*)d_in[0];
    const float* Wq = (const float*)d_in[1];
    const float* bq = (const float*)d_in[2];
    const float* Wk = (const float*)d_in[3];
    const float* bk = (const float*)d_in[4];
    const float* Wv = (const float*)d_in[5];
    const float* bv = (const float*)d_in[6];
    const float* Wo = (const float*)d_in[7];
    const float* bo = (const float*)d_in[8];
    float* out = (float*)d_out;
    (void)in_sizes; (void)n_in; (void)out_size;

    __half *qp, *kp, *vp, *yp, *xhp, *whp;
    cudaGetSymbolAddress((void**)&qp,  g_q);
    cudaGetSymbolAddress((void**)&kp,  g_k);
    cudaGetSymbolAddress((void**)&vp,  g_v);
    cudaGetSymbolAddress((void**)&yp,  g_y);
    cudaGetSymbolAddress((void**)&xhp, g_xh);
    cudaGetSymbolAddress((void**)&whp, g_wh);
    __half* who = whp + 3 * (size_t)CDIM * CDIM;

    cudaFuncSetAttribute(attn_kernel,
                         cudaFuncAttributeMaxDynamicSharedMemorySize, ATT_SMEM_B);
    cudaFuncSetAttribute(gemm_qkv_kernel,
                         cudaFuncAttributeMaxDynamicSharedMemorySize, GEMM_SMEM);
    cudaFuncSetAttribute(gemm_out_kernel,
                         cudaFuncAttributeMaxDynamicSharedMemorySize, GEMM_SMEM);

    const int TOT4 = NX4 + 4 * NW4;
    cvt_all_kernel<<<(TOT4 + 255) / 256, 256>>>(x, Wq, Wk, Wv, Wo, xhp, whp);

    gemm_qkv_kernel<<<dim3(24, MROWS / BM), 256, GEMM_SMEM>>>(xhp, whp, bq, bk, bv,
                                                              qp, kp, vp);

    attn_kernel<<<dim3(TSEQ / QR, NHEAD, BATCH), 256, ATT_SMEM_B>>>(qp, kp, vp, yp);

    gemm_out_kernel<<<dim3(CDIM / BN, MROWS / BM), 256, GEMM_SMEM>>>(yp, who, bo, out);
}